// round 14
// baseline (speedup 1.0000x reference)
#include <cuda_runtime.h>
#include <math.h>

#define Kc 16
#define Mc 32
#define PK (Mc * Kc * Kc)        /* 8192  */
#define PTOT (3 * PK + Kc)       /* 24592 */
#define SM_FLOATS (PK + Kc)      /* P and w in smem */
#define SMEM_BYTES (SM_FLOATS * 4)
#define THREADS 256

typedef unsigned long long u64;

// Precomputed params, transposed layout [i][j][k] (k fastest):
//   [0,PK)     P = -a^2            (a = s/sigma, s = sqrt(log2e/2))
//   [PK,2PK)   Q = -2ab            (b = -s*mu/sigma)
//   [2PK,3PK)  R = c - b^2         (c = (logW - log(sigma) - 0.5*log(2pi))*log2e)
//   [3PK,+K)   w = softmax(wk0_logits)
// so t = (P*x + Q)*x + R  ==  c - (a*x+b)^2  and entry = 2^t.
__device__ __align__(16) float g_P[PTOT];

// Q and R live in the constant bank (exactly 64KB total): warp-uniform
// addresses -> LDCU (uniform-register dest, floor 1/cyc) and UR operands in
// FFMA, which bypass both the LSU and the GPR bank-conflict limit.
__constant__ __align__(16) float c_Q[PK];
__constant__ __align__(16) float c_R[PK];

__global__ void prep_kernel(const float* __restrict__ wk0,
                            const float* __restrict__ W,
                            const float* __restrict__ mu,
                            const float* __restrict__ ps) {
    int idx = blockIdx.x * blockDim.x + threadIdx.x;
    if (idx >= PK) return;
    int i = idx >> 8;
    int k = (idx >> 4) & 15;
    int j = idx & 15;

    // log_softmax over axis=1 (the k index) of W_logits[i, :, j]
    int base = i * 256 + j;
    float m = -1e30f;
#pragma unroll
    for (int kk = 0; kk < Kc; kk++) m = fmaxf(m, W[base + kk * 16]);
    float ssum = 0.f;
#pragma unroll
    for (int kk = 0; kk < Kc; kk++) ssum += expf(W[base + kk * 16] - m);
    float logW = W[idx] - m - logf(ssum);

    float p = ps[idx];
    float sigma = (p > 20.f) ? p : log1pf(expf(p));   // softplus
    float inv = 1.f / sigma;
    float log_sigma = logf(sigma);

    const float LOG2E = 1.4426950408889634f;
    const float HALF_LOG_2PI = 0.9189385332046727f;
    const float S = 0.84932180028801907f;  // sqrt(LOG2E/2)

    float a_ = S * inv;
    float b_ = -S * mu[idx] * inv;
    float c_ = (logW - log_sigma - HALF_LOG_2PI) * LOG2E;

    int o = i * 256 + j * 16 + k;          // transposed [i][j][k]
    g_P[o]          = -a_ * a_;
    g_P[PK + o]     = -2.f * a_ * b_;
    g_P[2 * PK + o] = c_ - b_ * b_;

    if (idx < Kc) {
        float mw = -1e30f;
#pragma unroll
        for (int kk = 0; kk < Kc; kk++) mw = fmaxf(mw, wk0[kk]);
        float sw = 0.f;
#pragma unroll
        for (int kk = 0; kk < Kc; kk++) sw += expf(wk0[kk] - mw);
        g_P[3 * PK + idx] = expf(wk0[idx] - mw) / sw;
    }
}

__device__ __forceinline__ float ex2_approx(float t) {
    float r;
    asm("ex2.approx.ftz.f32 %0, %1;" : "=f"(r) : "f"(t));
    return r;
}
__device__ __forceinline__ u64 pack2(float lo, float hi) {
    u64 r; asm("mov.b64 %0, {%1, %2};" : "=l"(r) : "f"(lo), "f"(hi)); return r;
}
__device__ __forceinline__ void unpack2(u64 v, float& lo, float& hi) {
    asm("mov.b64 {%0, %1}, %2;" : "=f"(lo), "=f"(hi) : "l"(v));
}
__device__ __forceinline__ u64 fma2(u64 a, u64 b, u64 c) {
    u64 d; asm("fma.rn.f32x2 %0, %1, %2, %3;" : "=l"(d) : "l"(a), "l"(b), "l"(c)); return d;
}
__device__ __forceinline__ u64 add2(u64 a, u64 b) {
    u64 d; asm("add.rn.f32x2 %0, %1, %2;" : "=l"(d) : "l"(a), "l"(b)); return d;
}

// 2^t for a packed pair. poly==false -> MUFU ex2; poly==true -> FMA-pipe
// polynomial (round-to-int trick + deg-4 Horner + exponent splice).
// t is always negative here; only the low side needs clamping.
__device__ __forceinline__ u64 exp2pair(u64 t, bool poly,
                                        u64 MAGIC2, u64 NMAGIC2, u64 M1_2,
                                        u64 C1, u64 C2, u64 C3, u64 C4, u64 ONE2) {
    if (!poly) {
        float a, b; unpack2(t, a, b);
        return pack2(ex2_approx(a), ex2_approx(b));
    } else {
        u64 rr = add2(t, MAGIC2);            // 12582912 + round(t), exact
        u64 fi = add2(rr, NMAGIC2);          // round(t) as float pair
        u64 f  = fma2(fi, M1_2, t);          // f = t - round(t), in [-0.5, 0.5]
        u64 pp = fma2(C4, f, C3);
        pp = fma2(pp, f, C2);
        pp = fma2(pp, f, C1);
        pp = fma2(pp, f, ONE2);              // ~2^f
        float rl, rh; unpack2(rr, rl, rh);
        int il = __float_as_int(rl);
        int ih = __float_as_int(rh);
        il = max(il, 0x4B3FFF83);            // clamp i >= -125
        ih = max(ih, 0x4B3FFF83);
        float pl, ph; unpack2(pp, pl, ph);
        float el = __int_as_float((int)(__float_as_int(pl) + ((unsigned)il << 23)));
        float eh = __int_as_float((int)(__float_as_int(ph) + ((unsigned)ih << 23)));
        return pack2(el, eh);
    }
}

__global__ void __launch_bounds__(THREADS, 2)
ttg_main(const float* __restrict__ X, float* __restrict__ out, int N) {
    extern __shared__ float sm[];
    {
        const float4* src = (const float4*)g_P;        // P slab only
        float4* dst = (float4*)sm;
        for (int t = threadIdx.x; t < PK / 4; t += blockDim.x) dst[t] = src[t];
        if (threadIdx.x < Kc) sm[PK + threadIdx.x] = g_P[3 * PK + threadIdx.x];
    }
    __syncthreads();

    int n = blockIdx.x * blockDim.x + threadIdx.x;
    if (n >= N) return;

    const u64 MAGIC2  = pack2(12582912.f, 12582912.f);
    const u64 NMAGIC2 = pack2(-12582912.f, -12582912.f);
    const u64 M1_2    = pack2(-1.f, -1.f);
    const u64 ONE2    = pack2(1.f, 1.f);
    const u64 C1      = pack2(0.69314718f, 0.69314718f);
    const u64 C2      = pack2(0.24022650f, 0.24022650f);
    const u64 C3      = pack2(0.05550411f, 0.05550411f);
    const u64 C4      = pack2(0.00969518f, 0.00969518f);

    // v held as 8 packed pairs (k0..k15)
    u64 v2[8];
#pragma unroll
    for (int h = 0; h < 8; h++) v2[h] = pack2(sm[PK + 2 * h], sm[PK + 2 * h + 1]);

    const ulonglong2* s2 = (const ulonglong2*)sm;      // P
    const ulonglong2* q2 = (const ulonglong2*)c_Q;     // Q in constant bank
    const ulonglong2* r2 = (const ulonglong2*)c_R;     // R in constant bank
    const float* Xrow = X + (size_t)n * Mc;

    float xcur = Xrow[0];

#pragma unroll 1
    for (int i = 0; i < Mc; i++) {
        float xnext = Xrow[(i + 1) & 31];          // prefetch (wraps harmlessly on last iter)
        u64 x2 = pack2(xcur, xcur);

        u64 vn2[8];
#pragma unroll
        for (int h = 0; h < 8; h++) vn2[h] = 0ull;

        int ib = i * 64;  // 16B-unit index of row block i
#pragma unroll
        for (int jh = 0; jh < 8; jh++) {
            float va, vb; unpack2(v2[jh], va, vb);
#pragma unroll
            for (int jj = 0; jj < 2; jj++) {
                float vjs = jj ? vb : va;
                u64 vj2 = pack2(vjs, vjs);
                int j = 2 * jh + jj;
                // Poly split (compile-time): j%4==0 -> pairs 5,6,7 poly (3),
                // else pairs 6,7 (2). Avg 2.25/8 = 1152 poly pairs, balancing
                // MUFU (~652K cyc) against the UR-relieved FMA pipe (~636K).
                int pth = ((j & 3) == 0) ? 5 : 6;
                int jb = ib + j * 4;
#pragma unroll
                for (int q = 0; q < 4; q++) {
                    ulonglong2 Pq = s2[jb + q];
                    ulonglong2 Qq = q2[jb + q];
                    ulonglong2 Rq = r2[jb + q];
                    u64 t0 = fma2(fma2(Pq.x, x2, Qq.x), x2, Rq.x);
                    u64 t1 = fma2(fma2(Pq.y, x2, Qq.y), x2, Rq.y);
                    u64 r0 = exp2pair(t0, (2 * q)     >= pth, MAGIC2, NMAGIC2, M1_2, C1, C2, C3, C4, ONE2);
                    u64 r1 = exp2pair(t1, (2 * q + 1) >= pth, MAGIC2, NMAGIC2, M1_2, C1, C2, C3, C4, ONE2);
                    vn2[2 * q]     = fma2(r0, vj2, vn2[2 * q]);
                    vn2[2 * q + 1] = fma2(r1, vj2, vn2[2 * q + 1]);
                }
            }
        }
#pragma unroll
        for (int h = 0; h < 8; h++) v2[h] = vn2[h];
        xcur = xnext;
    }

    float s = 0.f;
#pragma unroll
    for (int h = 0; h < 8; h++) {
        float a, b; unpack2(v2[h], a, b);
        s += a + b;
    }
    out[n] = logf(s + 2.2204460492503131e-16f);
}

extern "C" void kernel_launch(void* const* d_in, const int* in_sizes, int n_in,
                              void* d_out, int out_size) {
    const float* X   = (const float*)d_in[0];
    const float* wk0 = (const float*)d_in[1];
    const float* W   = (const float*)d_in[2];
    const float* mu  = (const float*)d_in[3];
    const float* ps  = (const float*)d_in[4];
    float* out = (float*)d_out;
    int N = out_size;

    cudaFuncSetAttribute((const void*)ttg_main,
                         cudaFuncAttributeMaxDynamicSharedMemorySize, SMEM_BYTES);

    prep_kernel<<<(PK + 255) / 256, 256>>>(wk0, W, mu, ps);

    // Copy Q and R slabs of g_P into the constant bank: D2D memcpy nodes,
    // graph-capturable, no allocation.
    void* cqp = nullptr;
    void* crp = nullptr;
    void* gpp = nullptr;
    cudaGetSymbolAddress(&cqp, c_Q);
    cudaGetSymbolAddress(&crp, c_R);
    cudaGetSymbolAddress(&gpp, g_P);
    cudaMemcpyAsync(cqp, (const char*)gpp + (size_t)PK * sizeof(float),
                    (size_t)PK * sizeof(float), cudaMemcpyDeviceToDevice);
    cudaMemcpyAsync(crp, (const char*)gpp + (size_t)2 * PK * sizeof(float),
                    (size_t)PK * sizeof(float), cudaMemcpyDeviceToDevice);

    ttg_main<<<(N + THREADS - 1) / THREADS, THREADS, SMEM_BYTES>>>(X, out, N);
}

// round 15
// speedup vs baseline: 1.1167x; 1.1167x over previous
#include <cuda_runtime.h>
#include <math.h>

#define Kc 16
#define Mc 32
#define PK (Mc * Kc * Kc)        /* 8192  */
#define PTOT (3 * PK + Kc)       /* 24592 */
#define SM_FLOATS (PK + Kc)      /* P and w in smem */
#define SMEM_BYTES (SM_FLOATS * 4)
#define THREADS 256

typedef unsigned long long u64;

// Precomputed params, transposed layout [i][j][k] (k fastest):
//   [0,PK)     P = -a^2            (a = s/sigma, s = sqrt(log2e/2))
//   [PK,2PK)   Q = -2ab            (b = -s*mu/sigma)
//   [2PK,3PK)  R = c - b^2         (c = (logW - log(sigma) - 0.5*log(2pi))*log2e)
//   [3PK,+K)   w = softmax(wk0_logits)
// so t = (P*x + Q)*x + R  ==  c - (a*x+b)^2  and entry = 2^t.
__device__ __align__(16) float g_P[PTOT];

// Q and R live in the constant bank (exactly 64KB): warp-uniform LDC.128
// (measured-safe at ~8 cyc/op) keeps this traffic off the LSU; P stays in
// smem. This halves smem per CTA -> 3 CTAs/SM -> better issue efficiency.
__constant__ __align__(16) float c_Q[PK];
__constant__ __align__(16) float c_R[PK];

__global__ void prep_kernel(const float* __restrict__ wk0,
                            const float* __restrict__ W,
                            const float* __restrict__ mu,
                            const float* __restrict__ ps) {
    int idx = blockIdx.x * blockDim.x + threadIdx.x;
    if (idx >= PK) return;
    int i = idx >> 8;
    int k = (idx >> 4) & 15;
    int j = idx & 15;

    // log_softmax over axis=1 (the k index) of W_logits[i, :, j]
    int base = i * 256 + j;
    float m = -1e30f;
#pragma unroll
    for (int kk = 0; kk < Kc; kk++) m = fmaxf(m, W[base + kk * 16]);
    float ssum = 0.f;
#pragma unroll
    for (int kk = 0; kk < Kc; kk++) ssum += expf(W[base + kk * 16] - m);
    float logW = W[idx] - m - logf(ssum);

    float p = ps[idx];
    float sigma = (p > 20.f) ? p : log1pf(expf(p));   // softplus
    float inv = 1.f / sigma;
    float log_sigma = logf(sigma);

    const float LOG2E = 1.4426950408889634f;
    const float HALF_LOG_2PI = 0.9189385332046727f;
    const float S = 0.84932180028801907f;  // sqrt(LOG2E/2)

    float a_ = S * inv;
    float b_ = -S * mu[idx] * inv;
    float c_ = (logW - log_sigma - HALF_LOG_2PI) * LOG2E;

    int o = i * 256 + j * 16 + k;          // transposed [i][j][k]
    g_P[o]          = -a_ * a_;
    g_P[PK + o]     = -2.f * a_ * b_;
    g_P[2 * PK + o] = c_ - b_ * b_;

    if (idx < Kc) {
        float mw = -1e30f;
#pragma unroll
        for (int kk = 0; kk < Kc; kk++) mw = fmaxf(mw, wk0[kk]);
        float sw = 0.f;
#pragma unroll
        for (int kk = 0; kk < Kc; kk++) sw += expf(wk0[kk] - mw);
        g_P[3 * PK + idx] = expf(wk0[idx] - mw) / sw;
    }
}

__device__ __forceinline__ float ex2_approx(float t) {
    float r;
    asm("ex2.approx.ftz.f32 %0, %1;" : "=f"(r) : "f"(t));
    return r;
}
__device__ __forceinline__ u64 pack2(float lo, float hi) {
    u64 r; asm("mov.b64 %0, {%1, %2};" : "=l"(r) : "f"(lo), "f"(hi)); return r;
}
__device__ __forceinline__ void unpack2(u64 v, float& lo, float& hi) {
    asm("mov.b64 {%0, %1}, %2;" : "=f"(lo), "=f"(hi) : "l"(v));
}
__device__ __forceinline__ u64 fma2(u64 a, u64 b, u64 c) {
    u64 d; asm("fma.rn.f32x2 %0, %1, %2, %3;" : "=l"(d) : "l"(a), "l"(b), "l"(c)); return d;
}
__device__ __forceinline__ u64 add2(u64 a, u64 b) {
    u64 d; asm("add.rn.f32x2 %0, %1, %2;" : "=l"(d) : "l"(a), "l"(b)); return d;
}

// 2^t for a packed pair. poly==false -> MUFU ex2; poly==true -> FMA-pipe
// path: round-to-int trick + deg-3 Horner (c4/c5 Chebyshev-absorbed into
// c0..c3; max rel err ~8e-5) + integer exponent splice on the ALU pipe.
// t is always negative here; only the low side needs clamping.
__device__ __forceinline__ u64 exp2pair(u64 t, bool poly,
                                        u64 MAGIC2, u64 NMAGIC2, u64 M1_2,
                                        u64 C1, u64 C2, u64 C3, u64 C0) {
    if (!poly) {
        float a, b; unpack2(t, a, b);
        return pack2(ex2_approx(a), ex2_approx(b));
    } else {
        u64 rr = add2(t, MAGIC2);            // 12582912 + round(t), exact
        u64 fi = add2(rr, NMAGIC2);          // round(t) as float pair
        u64 f  = fma2(fi, M1_2, t);          // f = t - round(t), in [-0.5, 0.5]
        u64 pp = fma2(C3, f, C2);
        pp = fma2(pp, f, C1);
        pp = fma2(pp, f, C0);                // ~2^f (deg-3, absorbed coeffs)
        float rl, rh; unpack2(rr, rl, rh);
        int il = __float_as_int(rl);
        int ih = __float_as_int(rh);
        il = max(il, 0x4B3FFF83);            // clamp i >= -125
        ih = max(ih, 0x4B3FFF83);
        float pl, ph; unpack2(pp, pl, ph);
        float el = __int_as_float((int)(__float_as_int(pl) + ((unsigned)il << 23)));
        float eh = __int_as_float((int)(__float_as_int(ph) + ((unsigned)ih << 23)));
        return pack2(el, eh);
    }
}

__global__ void __launch_bounds__(THREADS, 2)
ttg_main(const float* __restrict__ X, float* __restrict__ out, int N) {
    extern __shared__ float sm[];
    {
        const float4* src = (const float4*)g_P;        // P slab only
        float4* dst = (float4*)sm;
        for (int t = threadIdx.x; t < PK / 4; t += blockDim.x) dst[t] = src[t];
        if (threadIdx.x < Kc) sm[PK + threadIdx.x] = g_P[3 * PK + threadIdx.x];
    }
    __syncthreads();

    int n = blockIdx.x * blockDim.x + threadIdx.x;
    if (n >= N) return;

    const u64 MAGIC2  = pack2(12582912.f, 12582912.f);
    const u64 NMAGIC2 = pack2(-12582912.f, -12582912.f);
    const u64 M1_2    = pack2(-1.f, -1.f);
    // deg-3 coefficients for 2^f on [-0.5,0.5] with c4,c5 absorbed
    const u64 C0      = pack2(0.99992490f, 0.99992490f);
    const u64 C1      = pack2(0.69312120f, 0.69312120f);
    const u64 C2      = pack2(0.24262901f, 0.24262901f);
    const u64 C3      = pack2(0.05592080f, 0.05592080f);

    // v held as 8 packed pairs (k0..k15)
    u64 v2[8];
#pragma unroll
    for (int h = 0; h < 8; h++) v2[h] = pack2(sm[PK + 2 * h], sm[PK + 2 * h + 1]);

    const ulonglong2* s2 = (const ulonglong2*)sm;      // P
    const ulonglong2* q2 = (const ulonglong2*)c_Q;     // Q in constant bank
    const ulonglong2* r2 = (const ulonglong2*)c_R;     // R in constant bank
    const float* Xrow = X + (size_t)n * Mc;

    float xcur = Xrow[0];

#pragma unroll 1
    for (int i = 0; i < Mc; i++) {
        float xnext = Xrow[(i + 1) & 31];          // prefetch (wraps harmlessly on last iter)
        u64 x2 = pack2(xcur, xcur);

        u64 vn2[8];
#pragma unroll
        for (int h = 0; h < 8; h++) vn2[h] = 0ull;

        int ib = i * 64;  // 16B-unit index of row block i
#pragma unroll
        for (int jh = 0; jh < 8; jh++) {
            float va, vb; unpack2(v2[jh], va, vb);
#pragma unroll
            for (int jj = 0; jj < 2; jj++) {
                float vjs = jj ? vb : va;
                u64 vj2 = pack2(vjs, vjs);
                int j = 2 * jh + jj;
                // Poly split (compile-time): j%4==3 -> pair 7 only (1 poly
                // pair), else pairs 6,7 (2). Avg 1.75/8 = 0.21875, balancing
                // MUFU (907K*(1-p) = 708K cyc) against the rt=3 FMA pipe
                // (510K + 907K*p = 708K cyc) with the 16-cyc deg-3 poly.
                int pth = ((j & 3) == 3) ? 7 : 6;
                int jb = ib + j * 4;
#pragma unroll
                for (int q = 0; q < 4; q++) {
                    ulonglong2 Pq = s2[jb + q];
                    ulonglong2 Qq = q2[jb + q];
                    ulonglong2 Rq = r2[jb + q];
                    u64 t0 = fma2(fma2(Pq.x, x2, Qq.x), x2, Rq.x);
                    u64 t1 = fma2(fma2(Pq.y, x2, Qq.y), x2, Rq.y);
                    u64 r0 = exp2pair(t0, (2 * q)     >= pth, MAGIC2, NMAGIC2, M1_2, C1, C2, C3, C0);
                    u64 r1 = exp2pair(t1, (2 * q + 1) >= pth, MAGIC2, NMAGIC2, M1_2, C1, C2, C3, C0);
                    vn2[2 * q]     = fma2(r0, vj2, vn2[2 * q]);
                    vn2[2 * q + 1] = fma2(r1, vj2, vn2[2 * q + 1]);
                }
            }
        }
#pragma unroll
        for (int h = 0; h < 8; h++) v2[h] = vn2[h];
        xcur = xnext;
    }

    float s = 0.f;
#pragma unroll
    for (int h = 0; h < 8; h++) {
        float a, b; unpack2(v2[h], a, b);
        s += a + b;
    }
    out[n] = logf(s + 2.2204460492503131e-16f);
}

extern "C" void kernel_launch(void* const* d_in, const int* in_sizes, int n_in,
                              void* d_out, int out_size) {
    const float* X   = (const float*)d_in[0];
    const float* wk0 = (const float*)d_in[1];
    const float* W   = (const float*)d_in[2];
    const float* mu  = (const float*)d_in[3];
    const float* ps  = (const float*)d_in[4];
    float* out = (float*)d_out;
    int N = out_size;

    cudaFuncSetAttribute((const void*)ttg_main,
                         cudaFuncAttributeMaxDynamicSharedMemorySize, SMEM_BYTES);

    prep_kernel<<<(PK + 255) / 256, 256>>>(wk0, W, mu, ps);

    // Copy Q and R slabs of g_P into the constant bank: D2D memcpy nodes,
    // graph-capturable, no allocation.
    void* cqp = nullptr;
    void* crp = nullptr;
    void* gpp = nullptr;
    cudaGetSymbolAddress(&cqp, c_Q);
    cudaGetSymbolAddress(&crp, c_R);
    cudaGetSymbolAddress(&gpp, g_P);
    cudaMemcpyAsync(cqp, (const char*)gpp + (size_t)PK * sizeof(float),
                    (size_t)PK * sizeof(float), cudaMemcpyDeviceToDevice);
    cudaMemcpyAsync(crp, (const char*)gpp + (size_t)2 * PK * sizeof(float),
                    (size_t)PK * sizeof(float), cudaMemcpyDeviceToDevice);

    ttg_main<<<(N + THREADS - 1) / THREADS, THREADS, SMEM_BYTES>>>(X, out, N);
}